// round 1
// baseline (speedup 1.0000x reference)
#include <cuda_runtime.h>

#define N_NODES 25000
#define N_EDGES 320000
#define F       64
#define NHEADS  5
#define NRELS   20
#define NBASES  10
#define OUTC    320   // NHEADS * F

// Scratch (static device globals — no allocation)
__device__ float g_z[N_NODES * F];                 // 6.4 MB
__device__ float g_attn[NRELS * NHEADS * 2 * F];   // [r][h][f(0..127)] 51.2 KB

// ---------------------------------------------------------------------------
// Kernel A: fused projection GEMM.
// Computes feat @ [fc_w | self_fc_w] -> (z into g_z, self_z into d_out).
// Tile 64x64, K=64 (full), 256 threads, 4x4 micro-tile per thread.
// grid = (ceil(N/64), 6): yTile 0 -> z, yTile 1..5 -> d_out cols.
// ---------------------------------------------------------------------------
__global__ void __launch_bounds__(256) proj_kernel(const float* __restrict__ feat,
                                                   const float* __restrict__ fc_w,
                                                   const float* __restrict__ self_fc_w,
                                                   float* __restrict__ out)
{
    __shared__ float As[64][65];
    __shared__ float Bs[64][65];
    const int tid = threadIdx.x;
    const int m0  = blockIdx.x * 64;
    const int yt  = blockIdx.y;

    // Load A tile (feat rows), float4, zero-padded past N_NODES
#pragma unroll
    for (int i = 0; i < 4; i++) {
        int v   = tid + i * 256;      // 0..1023 float4 slots
        int row = v >> 4;
        int c4  = (v & 15) * 4;
        int node = m0 + row;
        float4 a = make_float4(0.f, 0.f, 0.f, 0.f);
        if (node < N_NODES) a = *(const float4*)(feat + node * F + c4);
        As[row][c4 + 0] = a.x; As[row][c4 + 1] = a.y;
        As[row][c4 + 2] = a.z; As[row][c4 + 3] = a.w;
    }
    // Load B tile (weights)
#pragma unroll
    for (int i = 0; i < 4; i++) {
        int v  = tid + i * 256;
        int k  = v >> 4;
        int j4 = (v & 15) * 4;
        float4 b;
        if (yt == 0) b = *(const float4*)(fc_w + k * 64 + j4);
        else         b = *(const float4*)(self_fc_w + k * 320 + (yt - 1) * 64 + j4);
        Bs[k][j4 + 0] = b.x; Bs[k][j4 + 1] = b.y;
        Bs[k][j4 + 2] = b.z; Bs[k][j4 + 3] = b.w;
    }
    __syncthreads();

    const int tx = tid & 15, ty = tid >> 4;
    float acc[4][4] = {};
#pragma unroll
    for (int k = 0; k < 64; k++) {
        float a[4], b[4];
#pragma unroll
        for (int i = 0; i < 4; i++) a[i] = As[ty + 16 * i][k];
#pragma unroll
        for (int j = 0; j < 4; j++) b[j] = Bs[k][tx + 16 * j];
#pragma unroll
        for (int i = 0; i < 4; i++)
#pragma unroll
            for (int j = 0; j < 4; j++) acc[i][j] += a[i] * b[j];
    }

#pragma unroll
    for (int i = 0; i < 4; i++) {
        int node = m0 + ty + 16 * i;
        if (node >= N_NODES) continue;
#pragma unroll
        for (int j = 0; j < 4; j++) {
            int col = tx + 16 * j;
            if (yt == 0) g_z[node * F + col] = acc[i][j];
            else         out[node * OUTC + (yt - 1) * 64 + col] = acc[i][j];
        }
    }
}

// ---------------------------------------------------------------------------
// Kernel B: basis composition.  g_attn[r][h][f] = sum_b w_comp[r,b]*aw[b,f,h]
// grid = NRELS blocks x 128 threads (thread = f). Tiny.
// ---------------------------------------------------------------------------
__global__ void attn_comp_kernel(const float* __restrict__ aw,
                                 const float* __restrict__ w_comp)
{
    const int r = blockIdx.x;
    const int f = threadIdx.x;   // 0..127
    float wc[NBASES];
#pragma unroll
    for (int b = 0; b < NBASES; b++) wc[b] = w_comp[r * NBASES + b];
    float acc[NHEADS] = {};
#pragma unroll
    for (int b = 0; b < NBASES; b++) {
#pragma unroll
        for (int h = 0; h < NHEADS; h++)
            acc[h] += wc[b] * aw[(b * 128 + f) * NHEADS + h];
    }
#pragma unroll
    for (int h = 0; h < NHEADS; h++)
        g_attn[(r * NHEADS + h) * 128 + f] = acc[h];
}

// ---------------------------------------------------------------------------
// Kernel C: one warp per edge.
//   gather z[src], z[dst] -> 5-head dot with g_attn[etype] -> leaky_relu
//   -> scatter att[h]*z_src[f] into d_out[dst] via red.global.add.v4.f32
// 8 edges per 256-thread block; z_src staged in smem for the v4 scatter.
// ---------------------------------------------------------------------------
__global__ void __launch_bounds__(256) edge_kernel(const int* __restrict__ src,
                                                   const int* __restrict__ dst,
                                                   const int* __restrict__ etype,
                                                   float* __restrict__ out)
{
    __shared__ float smz[8][64];
    const int w    = threadIdx.x >> 5;
    const int lane = threadIdx.x & 31;
    const int e    = blockIdx.x * 8 + w;
    if (e >= N_EDGES) return;

    const int s = src[e];
    const int d = dst[e];
    const int r = etype[e];

    float2 zs = *(const float2*)(g_z + s * F + 2 * lane);
    float2 zd = *(const float2*)(g_z + d * F + 2 * lane);
    *(float2*)&smz[w][2 * lane] = zs;

    const float* wa = g_attn + r * (NHEADS * 128);
    float acc[NHEADS];
#pragma unroll
    for (int h = 0; h < NHEADS; h++) {
        float2 ws = *(const float2*)(wa + h * 128 + 2 * lane);
        float2 wd = *(const float2*)(wa + h * 128 + 64 + 2 * lane);
        acc[h] = zs.x * ws.x + zs.y * ws.y + zd.x * wd.x + zd.y * wd.y;
    }
    // butterfly reduce (all lanes end with the sum), then leaky_relu(0.01)
#pragma unroll
    for (int h = 0; h < NHEADS; h++) {
        float v = acc[h];
        v += __shfl_xor_sync(0xffffffffu, v, 16);
        v += __shfl_xor_sync(0xffffffffu, v, 8);
        v += __shfl_xor_sync(0xffffffffu, v, 4);
        v += __shfl_xor_sync(0xffffffffu, v, 2);
        v += __shfl_xor_sync(0xffffffffu, v, 1);
        acc[h] = v > 0.f ? v : 0.01f * v;
    }
    __syncwarp();

    float* ob = out + (long)d * OUTC;
    // 320 floats = 80 float4 chunks; lane handles chunks {lane, lane+32, lane+64}
#pragma unroll
    for (int t = 0; t < 3; t++) {
        int c = lane + 32 * t;
        if (c < 80) {
            int o = c * 4;
            int h = o >> 6;
            int f = o & 63;
            float a = acc[h];
            float4 zv = *(const float4*)&smz[w][f];
            asm volatile("red.global.add.v4.f32 [%0], {%1, %2, %3, %4};"
                         :: "l"(ob + o),
                            "f"(a * zv.x), "f"(a * zv.y),
                            "f"(a * zv.z), "f"(a * zv.w)
                         : "memory");
        }
    }
}

// ---------------------------------------------------------------------------
extern "C" void kernel_launch(void* const* d_in, const int* in_sizes, int n_in,
                              void* d_out, int out_size)
{
    const float* feat      = (const float*)d_in[0];
    const int*   src       = (const int*)  d_in[1];
    const int*   dst       = (const int*)  d_in[2];
    const int*   etype     = (const int*)  d_in[3];
    const float* fc_w      = (const float*)d_in[4];
    const float* self_fc_w = (const float*)d_in[5];
    const float* aw        = (const float*)d_in[6];
    const float* w_comp    = (const float*)d_in[7];
    float* out = (float*)d_out;

    dim3 g1((N_NODES + 63) / 64, 6);
    proj_kernel<<<g1, 256>>>(feat, fc_w, self_fc_w, out);     // z + self_z (re-inits d_out)
    attn_comp_kernel<<<NRELS, 128>>>(aw, w_comp);             // basis-composed attn matrices
    edge_kernel<<<(N_EDGES + 7) / 8, 256>>>(src, dst, etype, out);
}